// round 14
// baseline (speedup 1.0000x reference)
#include <cuda_runtime.h>
#include <cuda_bf16.h>

// 2-level 2D Haar DWT, fully fused, 256-bit memory ops end-to-end (R13).
//   loads : ld.global.L2::evict_last.v8.b32   (1KB/warp bursts)
//   L1 det: st.global.L2::evict_first.v8.b32  (1KB/warp bursts)
//   L2 sub: __stcs float4
// Tile: one thread owns 4 rows x 16 cols of input (64 floats in / 64 out).
// Mechanism: halve LTS transactions + LSU wavefronts per byte on both streams
// to raise effective HBM efficiency of the mixed R/W stream (traffic itself is
// already at the 201MB/replay floor; 4 cache-policy experiments were neutral).
//
// Input:  x (32,3,512,512) fp32 = 96 planes of 512x512.
// Output: a2|h2|v2|d2 (96,128,128 each) then h1|v1|d1 (96,256,256 each).

#define IN_H   512
#define IN_W   512
#define L1_W   256
#define L2_W   128
#define PLANES 96

#define N2 (PLANES * L2_W * L2_W)
#define N1 (PLANES * L1_W * L1_W)

#define OFF_A2 ((size_t)0)
#define OFF_H2 ((size_t)N2)
#define OFF_V2 ((size_t)2 * N2)
#define OFF_D2 ((size_t)3 * N2)
#define OFF_H1 ((size_t)4 * N2)
#define OFF_V1 ((size_t)4 * N2 + (size_t)N1)
#define OFF_D1 ((size_t)4 * N2 + (size_t)2 * N1)

struct f8 { float v[8]; };

__device__ __forceinline__ f8 ld8_el(const float* p) {
    unsigned a0,a1,a2,a3,a4,a5,a6,a7;
    asm("ld.global.L2::evict_last.v8.b32 {%0,%1,%2,%3,%4,%5,%6,%7}, [%8];"
        : "=r"(a0),"=r"(a1),"=r"(a2),"=r"(a3),
          "=r"(a4),"=r"(a5),"=r"(a6),"=r"(a7)
        : "l"(p));
    f8 r;
    r.v[0]=__uint_as_float(a0); r.v[1]=__uint_as_float(a1);
    r.v[2]=__uint_as_float(a2); r.v[3]=__uint_as_float(a3);
    r.v[4]=__uint_as_float(a4); r.v[5]=__uint_as_float(a5);
    r.v[6]=__uint_as_float(a6); r.v[7]=__uint_as_float(a7);
    return r;
}

__device__ __forceinline__ void st8_ef(float* p, const float* s) {
    asm volatile("st.global.L2::evict_first.v8.b32 [%0], {%1,%2,%3,%4,%5,%6,%7,%8};"
        :: "l"(p),
           "r"(__float_as_uint(s[0])), "r"(__float_as_uint(s[1])),
           "r"(__float_as_uint(s[2])), "r"(__float_as_uint(s[3])),
           "r"(__float_as_uint(s[4])), "r"(__float_as_uint(s[5])),
           "r"(__float_as_uint(s[6])), "r"(__float_as_uint(s[7]))
        : "memory");
}

__device__ __forceinline__ void haar4(float s00, float s01, float s10, float s11,
                                      float& a, float& h, float& v, float& d) {
    float st = s00 + s01;
    float dt = s00 - s01;
    float sb = s10 + s11;
    float db = s10 - s11;
    a = (st + sb) * 0.5f;
    h = (st - sb) * 0.5f;
    v = (dt + db) * 0.5f;
    d = (dt - db) * 0.5f;
}

__global__ __launch_bounds__(256)
void haar2_fused_v8v8_kernel(const float* __restrict__ x, float* __restrict__ out) {
    const int jx = threadIdx.x;                     // 0..31 : 16-col tile index
    const int i  = blockIdx.y * 8 + threadIdx.y;    // 0..127: level-2 row
    const int bc = blockIdx.z;                      // 0..95

    // ---- load 4 rows x 16 cols: two v8 per row, evict_last ----
    const float* p = x + (size_t)bc * (IN_H * IN_W)
                       + (size_t)(4 * i) * IN_W + 16 * jx;
    const f8 r0a = ld8_el(p + 0 * IN_W);
    const f8 r0b = ld8_el(p + 0 * IN_W + 8);
    const f8 r1a = ld8_el(p + 1 * IN_W);
    const f8 r1b = ld8_el(p + 1 * IN_W + 8);
    const f8 r2a = ld8_el(p + 2 * IN_W);
    const f8 r2b = ld8_el(p + 2 * IN_W + 8);
    const f8 r3a = ld8_el(p + 3 * IN_W);
    const f8 r3b = ld8_el(p + 3 * IN_W + 8);

    // ---- level 1: 8 col-pairs x 2 row-pairs ----
    float at[8], ht[8], vt[8], dt_[8];   // top row-pair  (L1 row 2i)
    float ab[8], hb[8], vb[8], db_[8];   // bottom pair   (L1 row 2i+1)
#pragma unroll
    for (int c = 0; c < 4; c++) {
        haar4(r0a.v[2*c], r0a.v[2*c+1], r1a.v[2*c], r1a.v[2*c+1],
              at[c], ht[c], vt[c], dt_[c]);
        haar4(r0b.v[2*c], r0b.v[2*c+1], r1b.v[2*c], r1b.v[2*c+1],
              at[c+4], ht[c+4], vt[c+4], dt_[c+4]);
        haar4(r2a.v[2*c], r2a.v[2*c+1], r3a.v[2*c], r3a.v[2*c+1],
              ab[c], hb[c], vb[c], db_[c]);
        haar4(r2b.v[2*c], r2b.v[2*c+1], r3b.v[2*c], r3b.v[2*c+1],
              ab[c+4], hb[c+4], vb[c+4], db_[c+4]);
    }

    // ---- level 2: 4 outputs per subband from the cA1 2x8 strip ----
    float a2[4], h2[4], v2[4], d2[4];
#pragma unroll
    for (int c = 0; c < 4; c++) {
        haar4(at[2*c], at[2*c+1], ab[2*c], ab[2*c+1],
              a2[c], h2[c], v2[c], d2[c]);
    }

    // ---- store level-1 details: v8 evict_first (L1 cols 8*jx..8*jx+7) ----
    const size_t l1r0 = (size_t)bc * (L1_W * L1_W) + (size_t)(2 * i) * L1_W + 8 * jx;
    const size_t l1r1 = l1r0 + L1_W;
    st8_ef(out + OFF_H1 + l1r0, ht);
    st8_ef(out + OFF_H1 + l1r1, hb);
    st8_ef(out + OFF_V1 + l1r0, vt);
    st8_ef(out + OFF_V1 + l1r1, vb);
    st8_ef(out + OFF_D1 + l1r0, dt_);
    st8_ef(out + OFF_D1 + l1r1, db_);

    // ---- store level-2 subbands: float4 streaming (L2 cols 4*jx..4*jx+3) ----
    const size_t l2row = (size_t)bc * (L2_W * L2_W) + (size_t)i * L2_W;
    __stcs(reinterpret_cast<float4*>(out + OFF_A2 + l2row) + jx,
           make_float4(a2[0], a2[1], a2[2], a2[3]));
    __stcs(reinterpret_cast<float4*>(out + OFF_H2 + l2row) + jx,
           make_float4(h2[0], h2[1], h2[2], h2[3]));
    __stcs(reinterpret_cast<float4*>(out + OFF_V2 + l2row) + jx,
           make_float4(v2[0], v2[1], v2[2], v2[3]));
    __stcs(reinterpret_cast<float4*>(out + OFF_D2 + l2row) + jx,
           make_float4(d2[0], d2[1], d2[2], d2[3]));
}

extern "C" void kernel_launch(void* const* d_in, const int* in_sizes, int n_in,
                              void* d_out, int out_size) {
    const float* x = (const float*)d_in[0];
    float* out     = (float*)d_out;
    dim3 block(32, 8, 1);
    dim3 grid(1, 16, 96);               // 1536 CTAs; block covers 32 rows x 512 cols
    haar2_fused_v8v8_kernel<<<grid, block>>>(x, out);
}